// round 2
// baseline (speedup 1.0000x reference)
#include <cuda_runtime.h>
#include <math.h>

#define H      24
#define D      128
#define DIM    3072
#define S_TXT  512
#define S_IMG  2048
#define S_TOT  2560
#define EPS    1e-6f

// ---------------- scratch (device globals; no allocations allowed) ----------
__device__ float g_Q[(size_t)H * S_TOT * D];   // [h][t][d], t: 0..511 txt, 512.. img
__device__ float g_K[(size_t)H * S_TOT * D];
__device__ float g_V[(size_t)H * S_TOT * D];
__device__ float g_A[(size_t)S_TOT * DIM];     // joint attn out, [t][h*D+d]

// ---------------------------------------------------------------------------
// SGEMM: C = A(MxDIM) * B(DIMxDIM) + bias, BM=BN=128, BK=8, 256 thr, 8x8/thr
// MODE 0: write head layout  C[(head*S_TOT + row_off + m)*D + (n&127)]
// MODE 1: write row-major    C[m*DIM + n]
// ---------------------------------------------------------------------------
template <int MODE>
__global__ void __launch_bounds__(256, 2)
sgemm_bias(const float* __restrict__ A, const float* __restrict__ B,
           const float* __restrict__ bias, float* __restrict__ C,
           int M, int row_off)
{
    __shared__ float As[2][8][132];   // [buf][k][m] (transposed), padded
    __shared__ float Bs[2][8][128];   // [buf][k][n]

    const int tid = threadIdx.x;
    const int bx = blockIdx.x;        // N tile (== head index for MODE 0)
    const int by = blockIdx.y;        // M tile
    const int m0 = by * 128;
    const int n0 = bx * 128;

    const int arow = tid >> 1;            // 0..127
    const int acol = (tid & 1) << 2;      // 0 or 4
    const int brow = tid >> 5;            // 0..7
    const int bcol = (tid & 31) << 2;     // 0..124

    const float* Aptr = A + (size_t)(m0 + arow) * DIM + acol;
    const float* Bptr = B + (size_t)brow * DIM + n0 + bcol;

    // preload k-tile 0 into buffer 0
    {
        float4 ra = *(const float4*)(Aptr);
        float4 rb = *(const float4*)(Bptr);
        As[0][acol + 0][arow] = ra.x;
        As[0][acol + 1][arow] = ra.y;
        As[0][acol + 2][arow] = ra.z;
        As[0][acol + 3][arow] = ra.w;
        *(float4*)&Bs[0][brow][bcol] = rb;
    }
    __syncthreads();

    float acc[8][8];
    #pragma unroll
    for (int i = 0; i < 8; ++i)
        #pragma unroll
        for (int j = 0; j < 8; ++j) acc[i][j] = 0.f;

    const int ty = tid >> 4;   // 0..15
    const int tx = tid & 15;   // 0..15

    const int NKT = DIM / 8;   // 384
    for (int kt = 0; kt < NKT; ++kt) {
        const int cb = kt & 1;
        const bool pre = (kt + 1 < NKT);
        float4 na, nb;
        if (pre) {
            na = *(const float4*)(Aptr + (kt + 1) * 8);
            nb = *(const float4*)(Bptr + (size_t)(kt + 1) * 8 * DIM);
        }
        #pragma unroll
        for (int kk = 0; kk < 8; ++kk) {
            float4 a0 = *(const float4*)&As[cb][kk][ty * 8];
            float4 a1 = *(const float4*)&As[cb][kk][ty * 8 + 4];
            float4 b0 = *(const float4*)&Bs[cb][kk][tx * 8];
            float4 b1 = *(const float4*)&Bs[cb][kk][tx * 8 + 4];
            float av[8] = {a0.x, a0.y, a0.z, a0.w, a1.x, a1.y, a1.z, a1.w};
            float bv[8] = {b0.x, b0.y, b0.z, b0.w, b1.x, b1.y, b1.z, b1.w};
            #pragma unroll
            for (int i = 0; i < 8; ++i)
                #pragma unroll
                for (int j = 0; j < 8; ++j)
                    acc[i][j] += av[i] * bv[j];
        }
        if (pre) {
            const int nbuf = cb ^ 1;
            As[nbuf][acol + 0][arow] = na.x;
            As[nbuf][acol + 1][arow] = na.y;
            As[nbuf][acol + 2][arow] = na.z;
            As[nbuf][acol + 3][arow] = na.w;
            *(float4*)&Bs[nbuf][brow][bcol] = nb;
        }
        __syncthreads();
    }

    // epilogue
    #pragma unroll
    for (int i = 0; i < 8; ++i) {
        const int m = m0 + ty * 8 + i;
        #pragma unroll
        for (int j = 0; j < 8; ++j) {
            const int col = tx * 8 + j;
            const int n = n0 + col;
            const float v = acc[i][j] + bias[n];
            if (MODE == 0)
                C[((size_t)bx * S_TOT + row_off + m) * D + col] = v;
            else
                C[(size_t)m * DIM + n] = v;
        }
    }
}

// ---------------------------------------------------------------------------
// RMSNorm + RoPE, one warp per (head, token) row of 128 floats, in place.
// t < S_TXT -> txt weights/cos/sin; else img (local position t - S_TXT).
// ---------------------------------------------------------------------------
__global__ void __launch_bounds__(256)
norm_rope(float* __restrict__ X,
          const float* __restrict__ w_img, const float* __restrict__ w_txt,
          const float* __restrict__ img_cos, const float* __restrict__ img_sin,
          const float* __restrict__ txt_cos, const float* __restrict__ txt_sin)
{
    const int warp = (blockIdx.x * blockDim.x + threadIdx.x) >> 5;
    const int lane = threadIdx.x & 31;
    if (warp >= H * S_TOT) return;
    const int t = warp % S_TOT;
    const int h = warp / S_TOT;
    float* row = X + ((size_t)h * S_TOT + t) * D;
    const int d0 = lane * 4;

    float4 x = *(const float4*)(row + d0);
    float ss = x.x * x.x + x.y * x.y + x.z * x.z + x.w * x.w;
    #pragma unroll
    for (int o = 16; o > 0; o >>= 1) ss += __shfl_xor_sync(0xffffffffu, ss, o);
    const float inv = rsqrtf(ss * (1.f / 128.f) + EPS);

    const float* w;
    const float* cs;
    const float* sn;
    if (t < S_TXT) { w = w_txt; cs = txt_cos + (size_t)t * D;          sn = txt_sin + (size_t)t * D; }
    else           { w = w_img; cs = img_cos + (size_t)(t - S_TXT) * D; sn = img_sin + (size_t)(t - S_TXT) * D; }

    float4 wv = *(const float4*)(w + d0);
    float4 c  = *(const float4*)(cs + d0);
    float4 s  = *(const float4*)(sn + d0);

    const float y0 = x.x * inv * wv.x;
    const float y1 = x.y * inv * wv.y;
    const float y2 = x.z * inv * wv.z;
    const float y3 = x.w * inv * wv.w;

    float4 o;
    o.x = y0 * c.x - y1 * s.x;
    o.y = y1 * c.y + y0 * s.y;
    o.z = y2 * c.z - y3 * s.z;
    o.w = y3 * c.w + y2 * s.w;
    *(float4*)(row + d0) = o;
}

// ---------------------------------------------------------------------------
// fp32 flash attention.  grid (S_TOT/64, H), 256 threads.
// BM=BN=64, D=128. Online softmax. Output -> joint layout g_A[t][h*D+d].
// ---------------------------------------------------------------------------
#define FA_BM 64
#define FA_BN 64
#define QS_STRIDE 132
#define VS_STRIDE 136
#define SS_STRIDE 68
#define FA_SMEM_FLOATS (FA_BM*QS_STRIDE + FA_BN*QS_STRIDE + FA_BN*VS_STRIDE + FA_BM*SS_STRIDE + 3*FA_BM)
#define FA_SMEM_BYTES  (FA_SMEM_FLOATS * sizeof(float))

__global__ void __launch_bounds__(256, 1)
flash_attn(const float* __restrict__ Q, const float* __restrict__ K,
           const float* __restrict__ V, float* __restrict__ Aout)
{
    extern __shared__ float sm[];
    float* Qs   = sm;
    float* Ks   = Qs + FA_BM * QS_STRIDE;
    float* Vs   = Ks + FA_BN * QS_STRIDE;
    float* Ss   = Vs + FA_BN * VS_STRIDE;
    float* m_s  = Ss + FA_BM * SS_STRIDE;
    float* l_s  = m_s + FA_BM;
    float* al_s = l_s + FA_BM;

    const int tid = threadIdx.x;
    const int h  = blockIdx.y;
    const int m0 = blockIdx.x * FA_BM;

    const float* Qg = Q + ((size_t)h * S_TOT + m0) * D;
    const float* Kg = K + (size_t)h * S_TOT * D;
    const float* Vg = V + (size_t)h * S_TOT * D;

    // load Q tile (64 x 128 floats = 2048 float4)
    #pragma unroll
    for (int i = 0; i < 8; ++i) {
        const int idx = tid + i * 256;
        const int r = idx >> 5;
        const int c = (idx & 31) << 2;
        *(float4*)(Qs + r * QS_STRIDE + c) = *(const float4*)(Qg + r * D + c);
    }
    if (tid < FA_BM) { m_s[tid] = -1e30f; l_s[tid] = 0.f; }

    float acc[4][8];
    #pragma unroll
    for (int i = 0; i < 4; ++i)
        #pragma unroll
        for (int j = 0; j < 8; ++j) acc[i][j] = 0.f;

    const int tr = tid >> 4;   // 0..15
    const int tc = tid & 15;   // 0..15
    const float scale = 0.08838834764831845f;   // 1/sqrt(128)

    __syncthreads();

    for (int kt = 0; kt < S_TOT / FA_BN; ++kt) {
        const float* kg = Kg + (size_t)kt * FA_BN * D;
        const float* vg = Vg + (size_t)kt * FA_BN * D;
        #pragma unroll
        for (int i = 0; i < 8; ++i) {
            const int idx = tid + i * 256;
            const int r = idx >> 5;
            const int c = (idx & 31) << 2;
            *(float4*)(Ks + r * QS_STRIDE + c) = *(const float4*)(kg + r * D + c);
            *(float4*)(Vs + r * VS_STRIDE + c) = *(const float4*)(vg + r * D + c);
        }
        __syncthreads();

        // S = Q K^T (each thread 4x4)
        float s_acc[4][4];
        #pragma unroll
        for (int i = 0; i < 4; ++i)
            #pragma unroll
            for (int j = 0; j < 4; ++j) s_acc[i][j] = 0.f;

        #pragma unroll 4
        for (int k = 0; k < D; k += 4) {
            float4 qv[4], kv[4];
            #pragma unroll
            for (int i = 0; i < 4; ++i) qv[i] = *(const float4*)(Qs + (tr * 4 + i) * QS_STRIDE + k);
            #pragma unroll
            for (int j = 0; j < 4; ++j) kv[j] = *(const float4*)(Ks + (tc * 4 + j) * QS_STRIDE + k);
            #pragma unroll
            for (int i = 0; i < 4; ++i)
                #pragma unroll
                for (int j = 0; j < 4; ++j)
                    s_acc[i][j] += qv[i].x * kv[j].x + qv[i].y * kv[j].y +
                                   qv[i].z * kv[j].z + qv[i].w * kv[j].w;
        }
        #pragma unroll
        for (int i = 0; i < 4; ++i)
            #pragma unroll
            for (int j = 0; j < 4; ++j)
                Ss[(tr * 4 + i) * SS_STRIDE + tc * 4 + j] = s_acc[i][j] * scale;
        __syncthreads();

        // online softmax (one thread per row)
        if (tid < FA_BM) {
            const int r = tid;
            float* srow = Ss + r * SS_STRIDE;
            const float mold = m_s[r];
            float mx = mold;
            #pragma unroll 8
            for (int n = 0; n < FA_BN; ++n) mx = fmaxf(mx, srow[n]);
            const float al = __expf(mold - mx);
            float sum = 0.f;
            #pragma unroll 8
            for (int n = 0; n < FA_BN; ++n) {
                const float p = __expf(srow[n] - mx);
                srow[n] = p;
                sum += p;
            }
            m_s[r] = mx;
            l_s[r] = l_s[r] * al + sum;
            al_s[r] = al;
        }
        __syncthreads();

        // rescale accumulators, then O += P * V  (each thread 4 rows x 8 cols)
        float alr[4];
        #pragma unroll
        for (int i = 0; i < 4; ++i) alr[i] = al_s[tr * 4 + i];
        #pragma unroll
        for (int i = 0; i < 4; ++i)
            #pragma unroll
            for (int j = 0; j < 8; ++j) acc[i][j] *= alr[i];

        #pragma unroll 4
        for (int n = 0; n < FA_BN; ++n) {
            float pp[4];
            #pragma unroll
            for (int i = 0; i < 4; ++i) pp[i] = Ss[(tr * 4 + i) * SS_STRIDE + n];
            float4 v0 = *(const float4*)(Vs + n * VS_STRIDE + tc * 8);
            float4 v1 = *(const float4*)(Vs + n * VS_STRIDE + tc * 8 + 4);
            float vv[8] = {v0.x, v0.y, v0.z, v0.w, v1.x, v1.y, v1.z, v1.w};
            #pragma unroll
            for (int i = 0; i < 4; ++i)
                #pragma unroll
                for (int j = 0; j < 8; ++j)
                    acc[i][j] += pp[i] * vv[j];
        }
        __syncthreads();
    }

    // epilogue: normalize by l, write joint layout
    #pragma unroll
    for (int i = 0; i < 4; ++i) {
        const int r = tr * 4 + i;
        const float inv = 1.f / l_s[r];
        const int t = m0 + r;
        float* outp = Aout + (size_t)t * DIM + h * D + tc * 8;
        float4 o0 = make_float4(acc[i][0] * inv, acc[i][1] * inv, acc[i][2] * inv, acc[i][3] * inv);
        float4 o1 = make_float4(acc[i][4] * inv, acc[i][5] * inv, acc[i][6] * inv, acc[i][7] * inv);
        *(float4*)(outp)     = o0;
        *(float4*)(outp + 4) = o1;
    }
}

// ---------------------------------------------------------------------------
extern "C" void kernel_launch(void* const* d_in, const int* in_sizes, int n_in,
                              void* d_out, int out_size)
{
    const float* hid     = (const float*)d_in[0];
    const float* enc     = (const float*)d_in[1];
    const float* img_cos = (const float*)d_in[2];
    const float* img_sin = (const float*)d_in[3];
    const float* txt_cos = (const float*)d_in[4];
    const float* txt_sin = (const float*)d_in[5];
    const float* wq  = (const float*)d_in[6];
    const float* bq  = (const float*)d_in[7];
    const float* wk  = (const float*)d_in[8];
    const float* bk  = (const float*)d_in[9];
    const float* wv  = (const float*)d_in[10];
    const float* bv  = (const float*)d_in[11];
    const float* awq = (const float*)d_in[12];
    const float* abq = (const float*)d_in[13];
    const float* awk = (const float*)d_in[14];
    const float* abk = (const float*)d_in[15];
    const float* awv = (const float*)d_in[16];
    const float* abv = (const float*)d_in[17];
    const float* wo  = (const float*)d_in[18];
    const float* bo  = (const float*)d_in[19];
    const float* awo = (const float*)d_in[20];
    const float* abo = (const float*)d_in[21];
    const float* nq  = (const float*)d_in[22];
    const float* nk  = (const float*)d_in[23];
    const float* anq = (const float*)d_in[24];
    const float* ank = (const float*)d_in[25];
    float* out = (float*)d_out;

    float *Qp, *Kp, *Vp, *Ap;
    cudaGetSymbolAddress((void**)&Qp, g_Q);
    cudaGetSymbolAddress((void**)&Kp, g_K);
    cudaGetSymbolAddress((void**)&Vp, g_V);
    cudaGetSymbolAddress((void**)&Ap, g_A);

    const dim3 gImg(DIM / 128, S_IMG / 128);
    const dim3 gTxt(DIM / 128, S_TXT / 128);

    // QKV projections into head layout (txt tokens at rows 0..511, img at 512..)
    sgemm_bias<0><<<gImg, 256>>>(hid, wq, bq, Qp, S_IMG, S_TXT);
    sgemm_bias<0><<<gImg, 256>>>(hid, wk, bk, Kp, S_IMG, S_TXT);
    sgemm_bias<0><<<gImg, 256>>>(hid, wv, bv, Vp, S_IMG, S_TXT);
    sgemm_bias<0><<<gTxt, 256>>>(enc, awq, abq, Qp, S_TXT, 0);
    sgemm_bias<0><<<gTxt, 256>>>(enc, awk, abk, Kp, S_TXT, 0);
    sgemm_bias<0><<<gTxt, 256>>>(enc, awv, abv, Vp, S_TXT, 0);

    // rmsnorm + rope on Q and K (V untouched)
    const int nr_blocks = (H * S_TOT) / 8;   // 8 warps per block
    norm_rope<<<nr_blocks, 256>>>(Qp, nq, anq, img_cos, img_sin, txt_cos, txt_sin);
    norm_rope<<<nr_blocks, 256>>>(Kp, nk, ank, img_cos, img_sin, txt_cos, txt_sin);

    // joint flash attention
    cudaFuncSetAttribute(flash_attn, cudaFuncAttributeMaxDynamicSharedMemorySize,
                         (int)FA_SMEM_BYTES);
    flash_attn<<<dim3(S_TOT / FA_BM, H), 256, FA_SMEM_BYTES>>>(Qp, Kp, Vp, Ap);

    // output projections: img rows of joint are 512.., txt rows 0..511
    sgemm_bias<1><<<gImg, 256>>>(Ap + (size_t)S_TXT * DIM, wo, bo, out, S_IMG, 0);
    sgemm_bias<1><<<gTxt, 256>>>(Ap, awo, abo, out + (size_t)S_IMG * DIM, S_TXT, 0);
}

// round 3
// speedup vs baseline: 1.0054x; 1.0054x over previous
#include <cuda_runtime.h>
#include <math.h>

#define H      24
#define D      128
#define DIM    3072
#define S_TXT  512
#define S_IMG  2048
#define S_TOT  2560
#define EPS    1e-6f

// ---------------- scratch (device globals; no allocations allowed) ----------
__device__ float g_Q[(size_t)H * S_TOT * D];   // [h][t][d], t: 0..511 txt, 512.. img
__device__ float g_K[(size_t)H * S_TOT * D];
__device__ float g_V[(size_t)H * S_TOT * D];
__device__ float g_A[(size_t)S_TOT * DIM];     // joint attn out, [t][h*D+d]

// ---------------------------------------------------------------------------
// SGEMM: C = A(MxDIM) * B(DIMxDIM) + bias, BM=BN=128, BK=8, 256 thr, 8x8/thr
// MODE 0: write head layout  C[(head*S_TOT + row_off + m)*D + (n&127)]
// MODE 1: write row-major    C[m*DIM + n]
// ---------------------------------------------------------------------------
template <int MODE>
__global__ void __launch_bounds__(256, 2)
sgemm_bias(const float* __restrict__ A, const float* __restrict__ B,
           const float* __restrict__ bias, float* __restrict__ C,
           int M, int row_off)
{
    __shared__ float As[2][8][132];   // [buf][k][m] (transposed), padded
    __shared__ float Bs[2][8][128];   // [buf][k][n]

    const int tid = threadIdx.x;
    const int bx = blockIdx.x;        // N tile (== head index for MODE 0)
    const int by = blockIdx.y;        // M tile
    const int m0 = by * 128;
    const int n0 = bx * 128;

    const int arow = tid >> 1;            // 0..127
    const int acol = (tid & 1) << 2;      // 0 or 4
    const int brow = tid >> 5;            // 0..7
    const int bcol = (tid & 31) << 2;     // 0..124

    const float* Aptr = A + (size_t)(m0 + arow) * DIM + acol;
    const float* Bptr = B + (size_t)brow * DIM + n0 + bcol;

    // preload k-tile 0 into buffer 0
    {
        float4 ra = *(const float4*)(Aptr);
        float4 rb = *(const float4*)(Bptr);
        As[0][acol + 0][arow] = ra.x;
        As[0][acol + 1][arow] = ra.y;
        As[0][acol + 2][arow] = ra.z;
        As[0][acol + 3][arow] = ra.w;
        *(float4*)&Bs[0][brow][bcol] = rb;
    }
    __syncthreads();

    float acc[8][8];
    #pragma unroll
    for (int i = 0; i < 8; ++i)
        #pragma unroll
        for (int j = 0; j < 8; ++j) acc[i][j] = 0.f;

    const int ty = tid >> 4;   // 0..15
    const int tx = tid & 15;   // 0..15

    const int NKT = DIM / 8;   // 384
    for (int kt = 0; kt < NKT; ++kt) {
        const int cb = kt & 1;
        const bool pre = (kt + 1 < NKT);
        float4 na, nb;
        if (pre) {
            na = *(const float4*)(Aptr + (kt + 1) * 8);
            nb = *(const float4*)(Bptr + (size_t)(kt + 1) * 8 * DIM);
        }
        #pragma unroll
        for (int kk = 0; kk < 8; ++kk) {
            float4 a0 = *(const float4*)&As[cb][kk][ty * 8];
            float4 a1 = *(const float4*)&As[cb][kk][ty * 8 + 4];
            float4 b0 = *(const float4*)&Bs[cb][kk][tx * 8];
            float4 b1 = *(const float4*)&Bs[cb][kk][tx * 8 + 4];
            float av[8] = {a0.x, a0.y, a0.z, a0.w, a1.x, a1.y, a1.z, a1.w};
            float bv[8] = {b0.x, b0.y, b0.z, b0.w, b1.x, b1.y, b1.z, b1.w};
            #pragma unroll
            for (int i = 0; i < 8; ++i)
                #pragma unroll
                for (int j = 0; j < 8; ++j)
                    acc[i][j] += av[i] * bv[j];
        }
        if (pre) {
            const int nbuf = cb ^ 1;
            As[nbuf][acol + 0][arow] = na.x;
            As[nbuf][acol + 1][arow] = na.y;
            As[nbuf][acol + 2][arow] = na.z;
            As[nbuf][acol + 3][arow] = na.w;
            *(float4*)&Bs[nbuf][brow][bcol] = nb;
        }
        __syncthreads();
    }

    // epilogue
    #pragma unroll
    for (int i = 0; i < 8; ++i) {
        const int m = m0 + ty * 8 + i;
        #pragma unroll
        for (int j = 0; j < 8; ++j) {
            const int col = tx * 8 + j;
            const int n = n0 + col;
            const float v = acc[i][j] + bias[n];
            if (MODE == 0)
                C[((size_t)bx * S_TOT + row_off + m) * D + col] = v;
            else
                C[(size_t)m * DIM + n] = v;
        }
    }
}

// ---------------------------------------------------------------------------
// RMSNorm + RoPE, one warp per (head, token) row of 128 floats, in place.
// t < S_TXT -> txt weights/cos/sin; else img (local position t - S_TXT).
// ---------------------------------------------------------------------------
__global__ void __launch_bounds__(256)
norm_rope(float* __restrict__ X,
          const float* __restrict__ w_img, const float* __restrict__ w_txt,
          const float* __restrict__ img_cos, const float* __restrict__ img_sin,
          const float* __restrict__ txt_cos, const float* __restrict__ txt_sin)
{
    const int warp = (blockIdx.x * blockDim.x + threadIdx.x) >> 5;
    const int lane = threadIdx.x & 31;
    if (warp >= H * S_TOT) return;
    const int t = warp % S_TOT;
    const int h = warp / S_TOT;
    float* row = X + ((size_t)h * S_TOT + t) * D;
    const int d0 = lane * 4;

    float4 x = *(const float4*)(row + d0);
    float ss = x.x * x.x + x.y * x.y + x.z * x.z + x.w * x.w;
    #pragma unroll
    for (int o = 16; o > 0; o >>= 1) ss += __shfl_xor_sync(0xffffffffu, ss, o);
    const float inv = rsqrtf(ss * (1.f / 128.f) + EPS);

    const float* w;
    const float* cs;
    const float* sn;
    if (t < S_TXT) { w = w_txt; cs = txt_cos + (size_t)t * D;          sn = txt_sin + (size_t)t * D; }
    else           { w = w_img; cs = img_cos + (size_t)(t - S_TXT) * D; sn = img_sin + (size_t)(t - S_TXT) * D; }

    float4 wv = *(const float4*)(w + d0);
    float4 c  = *(const float4*)(cs + d0);
    float4 s  = *(const float4*)(sn + d0);

    const float y0 = x.x * inv * wv.x;
    const float y1 = x.y * inv * wv.y;
    const float y2 = x.z * inv * wv.z;
    const float y3 = x.w * inv * wv.w;

    float4 o;
    o.x = y0 * c.x - y1 * s.x;
    o.y = y1 * c.y + y0 * s.y;
    o.z = y2 * c.z - y3 * s.z;
    o.w = y3 * c.w + y2 * s.w;
    *(float4*)(row + d0) = o;
}

// ---------------------------------------------------------------------------
// fp32 flash attention.  grid (S_TOT/64, H), 256 threads.
// BM=BN=64, D=128. Online softmax. Output -> joint layout g_A[t][h*D+d].
// ---------------------------------------------------------------------------
#define FA_BM 64
#define FA_BN 64
#define QS_STRIDE 132
#define VS_STRIDE 136
#define SS_STRIDE 68
#define FA_SMEM_FLOATS (FA_BM*QS_STRIDE + FA_BN*QS_STRIDE + FA_BN*VS_STRIDE + FA_BM*SS_STRIDE + 3*FA_BM)
#define FA_SMEM_BYTES  (FA_SMEM_FLOATS * sizeof(float))

__global__ void __launch_bounds__(256, 1)
flash_attn(const float* __restrict__ Q, const float* __restrict__ K,
           const float* __restrict__ V, float* __restrict__ Aout)
{
    extern __shared__ float sm[];
    float* Qs   = sm;
    float* Ks   = Qs + FA_BM * QS_STRIDE;
    float* Vs   = Ks + FA_BN * QS_STRIDE;
    float* Ss   = Vs + FA_BN * VS_STRIDE;
    float* m_s  = Ss + FA_BM * SS_STRIDE;
    float* l_s  = m_s + FA_BM;
    float* al_s = l_s + FA_BM;

    const int tid = threadIdx.x;
    const int h  = blockIdx.y;
    const int m0 = blockIdx.x * FA_BM;

    const float* Qg = Q + ((size_t)h * S_TOT + m0) * D;
    const float* Kg = K + (size_t)h * S_TOT * D;
    const float* Vg = V + (size_t)h * S_TOT * D;

    // load Q tile (64 x 128 floats = 2048 float4)
    #pragma unroll
    for (int i = 0; i < 8; ++i) {
        const int idx = tid + i * 256;
        const int r = idx >> 5;
        const int c = (idx & 31) << 2;
        *(float4*)(Qs + r * QS_STRIDE + c) = *(const float4*)(Qg + r * D + c);
    }
    if (tid < FA_BM) { m_s[tid] = -1e30f; l_s[tid] = 0.f; }

    float acc[4][8];
    #pragma unroll
    for (int i = 0; i < 4; ++i)
        #pragma unroll
        for (int j = 0; j < 8; ++j) acc[i][j] = 0.f;

    const int tr = tid >> 4;   // 0..15
    const int tc = tid & 15;   // 0..15
    const float scale = 0.08838834764831845f;   // 1/sqrt(128)

    __syncthreads();

    for (int kt = 0; kt < S_TOT / FA_BN; ++kt) {
        const float* kg = Kg + (size_t)kt * FA_BN * D;
        const float* vg = Vg + (size_t)kt * FA_BN * D;
        #pragma unroll
        for (int i = 0; i < 8; ++i) {
            const int idx = tid + i * 256;
            const int r = idx >> 5;
            const int c = (idx & 31) << 2;
            *(float4*)(Ks + r * QS_STRIDE + c) = *(const float4*)(kg + r * D + c);
            *(float4*)(Vs + r * VS_STRIDE + c) = *(const float4*)(vg + r * D + c);
        }
        __syncthreads();

        // S = Q K^T (each thread 4x4)
        float s_acc[4][4];
        #pragma unroll
        for (int i = 0; i < 4; ++i)
            #pragma unroll
            for (int j = 0; j < 4; ++j) s_acc[i][j] = 0.f;

        #pragma unroll 4
        for (int k = 0; k < D; k += 4) {
            float4 qv[4], kv[4];
            #pragma unroll
            for (int i = 0; i < 4; ++i) qv[i] = *(const float4*)(Qs + (tr * 4 + i) * QS_STRIDE + k);
            #pragma unroll
            for (int j = 0; j < 4; ++j) kv[j] = *(const float4*)(Ks + (tc * 4 + j) * QS_STRIDE + k);
            #pragma unroll
            for (int i = 0; i < 4; ++i)
                #pragma unroll
                for (int j = 0; j < 4; ++j)
                    s_acc[i][j] += qv[i].x * kv[j].x + qv[i].y * kv[j].y +
                                   qv[i].z * kv[j].z + qv[i].w * kv[j].w;
        }
        #pragma unroll
        for (int i = 0; i < 4; ++i)
            #pragma unroll
            for (int j = 0; j < 4; ++j)
                Ss[(tr * 4 + i) * SS_STRIDE + tc * 4 + j] = s_acc[i][j] * scale;
        __syncthreads();

        // online softmax (one thread per row)
        if (tid < FA_BM) {
            const int r = tid;
            float* srow = Ss + r * SS_STRIDE;
            const float mold = m_s[r];
            float mx = mold;
            #pragma unroll 8
            for (int n = 0; n < FA_BN; ++n) mx = fmaxf(mx, srow[n]);
            const float al = __expf(mold - mx);
            float sum = 0.f;
            #pragma unroll 8
            for (int n = 0; n < FA_BN; ++n) {
                const float p = __expf(srow[n] - mx);
                srow[n] = p;
                sum += p;
            }
            m_s[r] = mx;
            l_s[r] = l_s[r] * al + sum;
            al_s[r] = al;
        }
        __syncthreads();

        // rescale accumulators, then O += P * V  (each thread 4 rows x 8 cols)
        float alr[4];
        #pragma unroll
        for (int i = 0; i < 4; ++i) alr[i] = al_s[tr * 4 + i];
        #pragma unroll
        for (int i = 0; i < 4; ++i)
            #pragma unroll
            for (int j = 0; j < 8; ++j) acc[i][j] *= alr[i];

        #pragma unroll 4
        for (int n = 0; n < FA_BN; ++n) {
            float pp[4];
            #pragma unroll
            for (int i = 0; i < 4; ++i) pp[i] = Ss[(tr * 4 + i) * SS_STRIDE + n];
            float4 v0 = *(const float4*)(Vs + n * VS_STRIDE + tc * 8);
            float4 v1 = *(const float4*)(Vs + n * VS_STRIDE + tc * 8 + 4);
            float vv[8] = {v0.x, v0.y, v0.z, v0.w, v1.x, v1.y, v1.z, v1.w};
            #pragma unroll
            for (int i = 0; i < 4; ++i)
                #pragma unroll
                for (int j = 0; j < 8; ++j)
                    acc[i][j] += pp[i] * vv[j];
        }
        __syncthreads();
    }

    // epilogue: normalize by l, write joint layout
    #pragma unroll
    for (int i = 0; i < 4; ++i) {
        const int r = tr * 4 + i;
        const float inv = 1.f / l_s[r];
        const int t = m0 + r;
        float* outp = Aout + (size_t)t * DIM + h * D + tc * 8;
        float4 o0 = make_float4(acc[i][0] * inv, acc[i][1] * inv, acc[i][2] * inv, acc[i][3] * inv);
        float4 o1 = make_float4(acc[i][4] * inv, acc[i][5] * inv, acc[i][6] * inv, acc[i][7] * inv);
        *(float4*)(outp)     = o0;
        *(float4*)(outp + 4) = o1;
    }
}

// ---------------------------------------------------------------------------
extern "C" void kernel_launch(void* const* d_in, const int* in_sizes, int n_in,
                              void* d_out, int out_size)
{
    const float* hid     = (const float*)d_in[0];
    const float* enc     = (const float*)d_in[1];
    const float* img_cos = (const float*)d_in[2];
    const float* img_sin = (const float*)d_in[3];
    const float* txt_cos = (const float*)d_in[4];
    const float* txt_sin = (const float*)d_in[5];
    const float* wq  = (const float*)d_in[6];
    const float* bq  = (const float*)d_in[7];
    const float* wk  = (const float*)d_in[8];
    const float* bk  = (const float*)d_in[9];
    const float* wv  = (const float*)d_in[10];
    const float* bv  = (const float*)d_in[11];
    const float* awq = (const float*)d_in[12];
    const float* abq = (const float*)d_in[13];
    const float* awk = (const float*)d_in[14];
    const float* abk = (const float*)d_in[15];
    const float* awv = (const float*)d_in[16];
    const float* abv = (const float*)d_in[17];
    const float* wo  = (const float*)d_in[18];
    const float* bo  = (const float*)d_in[19];
    const float* awo = (const float*)d_in[20];
    const float* abo = (const float*)d_in[21];
    const float* nq  = (const float*)d_in[22];
    const float* nk  = (const float*)d_in[23];
    const float* anq = (const float*)d_in[24];
    const float* ank = (const float*)d_in[25];
    float* out = (float*)d_out;

    float *Qp, *Kp, *Vp, *Ap;
    cudaGetSymbolAddress((void**)&Qp, g_Q);
    cudaGetSymbolAddress((void**)&Kp, g_K);
    cudaGetSymbolAddress((void**)&Vp, g_V);
    cudaGetSymbolAddress((void**)&Ap, g_A);

    const dim3 gImg(DIM / 128, S_IMG / 128);
    const dim3 gTxt(DIM / 128, S_TXT / 128);

    // QKV projections into head layout (txt tokens at rows 0..511, img at 512..)
    sgemm_bias<0><<<gImg, 256>>>(hid, wq, bq, Qp, S_IMG, S_TXT);
    sgemm_bias<0><<<gImg, 256>>>(hid, wk, bk, Kp, S_IMG, S_TXT);
    sgemm_bias<0><<<gImg, 256>>>(hid, wv, bv, Vp, S_IMG, S_TXT);
    sgemm_bias<0><<<gTxt, 256>>>(enc, awq, abq, Qp, S_TXT, 0);
    sgemm_bias<0><<<gTxt, 256>>>(enc, awk, abk, Kp, S_TXT, 0);
    sgemm_bias<0><<<gTxt, 256>>>(enc, awv, abv, Vp, S_TXT, 0);

    // rmsnorm + rope on Q and K (V untouched)
    const int nr_blocks = (H * S_TOT) / 8;   // 8 warps per block
    norm_rope<<<nr_blocks, 256>>>(Qp, nq, anq, img_cos, img_sin, txt_cos, txt_sin);
    norm_rope<<<nr_blocks, 256>>>(Kp, nk, ank, img_cos, img_sin, txt_cos, txt_sin);

    // joint flash attention
    cudaFuncSetAttribute(flash_attn, cudaFuncAttributeMaxDynamicSharedMemorySize,
                         (int)FA_SMEM_BYTES);
    flash_attn<<<dim3(S_TOT / FA_BM, H), 256, FA_SMEM_BYTES>>>(Qp, Kp, Vp, Ap);

    // output projections: img rows of joint are 512.., txt rows 0..511
    sgemm_bias<1><<<gImg, 256>>>(Ap + (size_t)S_TXT * DIM, wo, bo, out, S_IMG, 0);
    sgemm_bias<1><<<gTxt, 256>>>(Ap, awo, abo, out + (size_t)S_IMG * DIM, S_TXT, 0);
}

// round 4
// speedup vs baseline: 1.0056x; 1.0002x over previous
#include <cuda_runtime.h>
#include <math.h>

#define H      24
#define D      128
#define DIM    3072
#define S_TXT  512
#define S_IMG  2048
#define S_TOT  2560
#define EPS    1e-6f

// ---------------- scratch (device globals; no allocations allowed) ----------
__device__ float g_Q[(size_t)H * S_TOT * D];   // [h][t][d], t: 0..511 txt, 512.. img
__device__ float g_K[(size_t)H * S_TOT * D];
__device__ float g_V[(size_t)H * S_TOT * D];
__device__ float g_A[(size_t)S_TOT * DIM];     // joint attn out, [t][h*D+d]

// ---------------------------------------------------------------------------
// SGEMM: C = A(MxDIM) * B(DIMxDIM) + bias, BM=BN=128, BK=8, 256 thr, 8x8/thr
// MODE 0: write head layout  C[(head*S_TOT + row_off + m)*D + (n&127)]
// MODE 1: write row-major    C[m*DIM + n]
// ---------------------------------------------------------------------------
template <int MODE>
__global__ void __launch_bounds__(256, 2)
sgemm_bias(const float* __restrict__ A, const float* __restrict__ B,
           const float* __restrict__ bias, float* __restrict__ C,
           int M, int row_off)
{
    __shared__ float As[2][8][132];   // [buf][k][m] (transposed), padded
    __shared__ float Bs[2][8][128];   // [buf][k][n]

    const int tid = threadIdx.x;
    const int bx = blockIdx.x;        // N tile (== head index for MODE 0)
    const int by = blockIdx.y;        // M tile
    const int m0 = by * 128;
    const int n0 = bx * 128;

    const int arow = tid >> 1;            // 0..127
    const int acol = (tid & 1) << 2;      // 0 or 4
    const int brow = tid >> 5;            // 0..7
    const int bcol = (tid & 31) << 2;     // 0..124

    const float* Aptr = A + (size_t)(m0 + arow) * DIM + acol;
    const float* Bptr = B + (size_t)brow * DIM + n0 + bcol;

    // preload k-tile 0 into buffer 0
    {
        float4 ra = *(const float4*)(Aptr);
        float4 rb = *(const float4*)(Bptr);
        As[0][acol + 0][arow] = ra.x;
        As[0][acol + 1][arow] = ra.y;
        As[0][acol + 2][arow] = ra.z;
        As[0][acol + 3][arow] = ra.w;
        *(float4*)&Bs[0][brow][bcol] = rb;
    }
    __syncthreads();

    float acc[8][8];
    #pragma unroll
    for (int i = 0; i < 8; ++i)
        #pragma unroll
        for (int j = 0; j < 8; ++j) acc[i][j] = 0.f;

    const int ty = tid >> 4;   // 0..15
    const int tx = tid & 15;   // 0..15

    const int NKT = DIM / 8;   // 384
    for (int kt = 0; kt < NKT; ++kt) {
        const int cb = kt & 1;
        const bool pre = (kt + 1 < NKT);
        float4 na, nb;
        if (pre) {
            na = *(const float4*)(Aptr + (kt + 1) * 8);
            nb = *(const float4*)(Bptr + (size_t)(kt + 1) * 8 * DIM);
        }
        #pragma unroll
        for (int kk = 0; kk < 8; ++kk) {
            float4 a0 = *(const float4*)&As[cb][kk][ty * 8];
            float4 a1 = *(const float4*)&As[cb][kk][ty * 8 + 4];
            float4 b0 = *(const float4*)&Bs[cb][kk][tx * 8];
            float4 b1 = *(const float4*)&Bs[cb][kk][tx * 8 + 4];
            float av[8] = {a0.x, a0.y, a0.z, a0.w, a1.x, a1.y, a1.z, a1.w};
            float bv[8] = {b0.x, b0.y, b0.z, b0.w, b1.x, b1.y, b1.z, b1.w};
            #pragma unroll
            for (int i = 0; i < 8; ++i)
                #pragma unroll
                for (int j = 0; j < 8; ++j)
                    acc[i][j] += av[i] * bv[j];
        }
        if (pre) {
            const int nbuf = cb ^ 1;
            As[nbuf][acol + 0][arow] = na.x;
            As[nbuf][acol + 1][arow] = na.y;
            As[nbuf][acol + 2][arow] = na.z;
            As[nbuf][acol + 3][arow] = na.w;
            *(float4*)&Bs[nbuf][brow][bcol] = nb;
        }
        __syncthreads();
    }

    // epilogue
    #pragma unroll
    for (int i = 0; i < 8; ++i) {
        const int m = m0 + ty * 8 + i;
        #pragma unroll
        for (int j = 0; j < 8; ++j) {
            const int col = tx * 8 + j;
            const int n = n0 + col;
            const float v = acc[i][j] + bias[n];
            if (MODE == 0)
                C[((size_t)bx * S_TOT + row_off + m) * D + col] = v;
            else
                C[(size_t)m * DIM + n] = v;
        }
    }
}

// ---------------------------------------------------------------------------
// RMSNorm + RoPE, one warp per (head, token) row of 128 floats, in place.
// t < S_TXT -> txt weights/cos/sin; else img (local position t - S_TXT).
// ---------------------------------------------------------------------------
__global__ void __launch_bounds__(256)
norm_rope(float* __restrict__ X,
          const float* __restrict__ w_img, const float* __restrict__ w_txt,
          const float* __restrict__ img_cos, const float* __restrict__ img_sin,
          const float* __restrict__ txt_cos, const float* __restrict__ txt_sin)
{
    const int warp = (blockIdx.x * blockDim.x + threadIdx.x) >> 5;
    const int lane = threadIdx.x & 31;
    if (warp >= H * S_TOT) return;
    const int t = warp % S_TOT;
    const int h = warp / S_TOT;
    float* row = X + ((size_t)h * S_TOT + t) * D;
    const int d0 = lane * 4;

    float4 x = *(const float4*)(row + d0);
    float ss = x.x * x.x + x.y * x.y + x.z * x.z + x.w * x.w;
    #pragma unroll
    for (int o = 16; o > 0; o >>= 1) ss += __shfl_xor_sync(0xffffffffu, ss, o);
    const float inv = rsqrtf(ss * (1.f / 128.f) + EPS);

    const float* w;
    const float* cs;
    const float* sn;
    if (t < S_TXT) { w = w_txt; cs = txt_cos + (size_t)t * D;          sn = txt_sin + (size_t)t * D; }
    else           { w = w_img; cs = img_cos + (size_t)(t - S_TXT) * D; sn = img_sin + (size_t)(t - S_TXT) * D; }

    float4 wv = *(const float4*)(w + d0);
    float4 c  = *(const float4*)(cs + d0);
    float4 s  = *(const float4*)(sn + d0);

    const float y0 = x.x * inv * wv.x;
    const float y1 = x.y * inv * wv.y;
    const float y2 = x.z * inv * wv.z;
    const float y3 = x.w * inv * wv.w;

    float4 o;
    o.x = y0 * c.x - y1 * s.x;
    o.y = y1 * c.y + y0 * s.y;
    o.z = y2 * c.z - y3 * s.z;
    o.w = y3 * c.w + y2 * s.w;
    *(float4*)(row + d0) = o;
}

// ---------------------------------------------------------------------------
// fp32 flash attention.  grid (S_TOT/64, H), 256 threads.
// BM=BN=64, D=128. Online softmax. Output -> joint layout g_A[t][h*D+d].
// ---------------------------------------------------------------------------
#define FA_BM 64
#define FA_BN 64
#define QS_STRIDE 132
#define VS_STRIDE 136
#define SS_STRIDE 68
#define FA_SMEM_FLOATS (FA_BM*QS_STRIDE + FA_BN*QS_STRIDE + FA_BN*VS_STRIDE + FA_BM*SS_STRIDE + 3*FA_BM)
#define FA_SMEM_BYTES  (FA_SMEM_FLOATS * sizeof(float))

__global__ void __launch_bounds__(256, 1)
flash_attn(const float* __restrict__ Q, const float* __restrict__ K,
           const float* __restrict__ V, float* __restrict__ Aout)
{
    extern __shared__ float sm[];
    float* Qs   = sm;
    float* Ks   = Qs + FA_BM * QS_STRIDE;
    float* Vs   = Ks + FA_BN * QS_STRIDE;
    float* Ss   = Vs + FA_BN * VS_STRIDE;
    float* m_s  = Ss + FA_BM * SS_STRIDE;
    float* l_s  = m_s + FA_BM;
    float* al_s = l_s + FA_BM;

    const int tid = threadIdx.x;
    const int h  = blockIdx.y;
    const int m0 = blockIdx.x * FA_BM;

    const float* Qg = Q + ((size_t)h * S_TOT + m0) * D;
    const float* Kg = K + (size_t)h * S_TOT * D;
    const float* Vg = V + (size_t)h * S_TOT * D;

    // load Q tile (64 x 128 floats = 2048 float4)
    #pragma unroll
    for (int i = 0; i < 8; ++i) {
        const int idx = tid + i * 256;
        const int r = idx >> 5;
        const int c = (idx & 31) << 2;
        *(float4*)(Qs + r * QS_STRIDE + c) = *(const float4*)(Qg + r * D + c);
    }
    if (tid < FA_BM) { m_s[tid] = -1e30f; l_s[tid] = 0.f; }

    float acc[4][8];
    #pragma unroll
    for (int i = 0; i < 4; ++i)
        #pragma unroll
        for (int j = 0; j < 8; ++j) acc[i][j] = 0.f;

    const int tr = tid >> 4;   // 0..15
    const int tc = tid & 15;   // 0..15
    const float scale = 0.08838834764831845f;   // 1/sqrt(128)

    __syncthreads();

    for (int kt = 0; kt < S_TOT / FA_BN; ++kt) {
        const float* kg = Kg + (size_t)kt * FA_BN * D;
        const float* vg = Vg + (size_t)kt * FA_BN * D;
        #pragma unroll
        for (int i = 0; i < 8; ++i) {
            const int idx = tid + i * 256;
            const int r = idx >> 5;
            const int c = (idx & 31) << 2;
            *(float4*)(Ks + r * QS_STRIDE + c) = *(const float4*)(kg + r * D + c);
            *(float4*)(Vs + r * VS_STRIDE + c) = *(const float4*)(vg + r * D + c);
        }
        __syncthreads();

        // S = Q K^T (each thread 4x4)
        float s_acc[4][4];
        #pragma unroll
        for (int i = 0; i < 4; ++i)
            #pragma unroll
            for (int j = 0; j < 4; ++j) s_acc[i][j] = 0.f;

        #pragma unroll 4
        for (int k = 0; k < D; k += 4) {
            float4 qv[4], kv[4];
            #pragma unroll
            for (int i = 0; i < 4; ++i) qv[i] = *(const float4*)(Qs + (tr * 4 + i) * QS_STRIDE + k);
            #pragma unroll
            for (int j = 0; j < 4; ++j) kv[j] = *(const float4*)(Ks + (tc * 4 + j) * QS_STRIDE + k);
            #pragma unroll
            for (int i = 0; i < 4; ++i)
                #pragma unroll
                for (int j = 0; j < 4; ++j)
                    s_acc[i][j] += qv[i].x * kv[j].x + qv[i].y * kv[j].y +
                                   qv[i].z * kv[j].z + qv[i].w * kv[j].w;
        }
        #pragma unroll
        for (int i = 0; i < 4; ++i)
            #pragma unroll
            for (int j = 0; j < 4; ++j)
                Ss[(tr * 4 + i) * SS_STRIDE + tc * 4 + j] = s_acc[i][j] * scale;
        __syncthreads();

        // online softmax (one thread per row)
        if (tid < FA_BM) {
            const int r = tid;
            float* srow = Ss + r * SS_STRIDE;
            const float mold = m_s[r];
            float mx = mold;
            #pragma unroll 8
            for (int n = 0; n < FA_BN; ++n) mx = fmaxf(mx, srow[n]);
            const float al = __expf(mold - mx);
            float sum = 0.f;
            #pragma unroll 8
            for (int n = 0; n < FA_BN; ++n) {
                const float p = __expf(srow[n] - mx);
                srow[n] = p;
                sum += p;
            }
            m_s[r] = mx;
            l_s[r] = l_s[r] * al + sum;
            al_s[r] = al;
        }
        __syncthreads();

        // rescale accumulators, then O += P * V  (each thread 4 rows x 8 cols)
        float alr[4];
        #pragma unroll
        for (int i = 0; i < 4; ++i) alr[i] = al_s[tr * 4 + i];
        #pragma unroll
        for (int i = 0; i < 4; ++i)
            #pragma unroll
            for (int j = 0; j < 8; ++j) acc[i][j] *= alr[i];

        #pragma unroll 4
        for (int n = 0; n < FA_BN; ++n) {
            float pp[4];
            #pragma unroll
            for (int i = 0; i < 4; ++i) pp[i] = Ss[(tr * 4 + i) * SS_STRIDE + n];
            float4 v0 = *(const float4*)(Vs + n * VS_STRIDE + tc * 8);
            float4 v1 = *(const float4*)(Vs + n * VS_STRIDE + tc * 8 + 4);
            float vv[8] = {v0.x, v0.y, v0.z, v0.w, v1.x, v1.y, v1.z, v1.w};
            #pragma unroll
            for (int i = 0; i < 4; ++i)
                #pragma unroll
                for (int j = 0; j < 8; ++j)
                    acc[i][j] += pp[i] * vv[j];
        }
        __syncthreads();
    }

    // epilogue: normalize by l, write joint layout
    #pragma unroll
    for (int i = 0; i < 4; ++i) {
        const int r = tr * 4 + i;
        const float inv = 1.f / l_s[r];
        const int t = m0 + r;
        float* outp = Aout + (size_t)t * DIM + h * D + tc * 8;
        float4 o0 = make_float4(acc[i][0] * inv, acc[i][1] * inv, acc[i][2] * inv, acc[i][3] * inv);
        float4 o1 = make_float4(acc[i][4] * inv, acc[i][5] * inv, acc[i][6] * inv, acc[i][7] * inv);
        *(float4*)(outp)     = o0;
        *(float4*)(outp + 4) = o1;
    }
}

// ---------------------------------------------------------------------------
extern "C" void kernel_launch(void* const* d_in, const int* in_sizes, int n_in,
                              void* d_out, int out_size)
{
    const float* hid     = (const float*)d_in[0];
    const float* enc     = (const float*)d_in[1];
    const float* img_cos = (const float*)d_in[2];
    const float* img_sin = (const float*)d_in[3];
    const float* txt_cos = (const float*)d_in[4];
    const float* txt_sin = (const float*)d_in[5];
    const float* wq  = (const float*)d_in[6];
    const float* bq  = (const float*)d_in[7];
    const float* wk  = (const float*)d_in[8];
    const float* bk  = (const float*)d_in[9];
    const float* wv  = (const float*)d_in[10];
    const float* bv  = (const float*)d_in[11];
    const float* awq = (const float*)d_in[12];
    const float* abq = (const float*)d_in[13];
    const float* awk = (const float*)d_in[14];
    const float* abk = (const float*)d_in[15];
    const float* awv = (const float*)d_in[16];
    const float* abv = (const float*)d_in[17];
    const float* wo  = (const float*)d_in[18];
    const float* bo  = (const float*)d_in[19];
    const float* awo = (const float*)d_in[20];
    const float* abo = (const float*)d_in[21];
    const float* nq  = (const float*)d_in[22];
    const float* nk  = (const float*)d_in[23];
    const float* anq = (const float*)d_in[24];
    const float* ank = (const float*)d_in[25];
    float* out = (float*)d_out;

    float *Qp, *Kp, *Vp, *Ap;
    cudaGetSymbolAddress((void**)&Qp, g_Q);
    cudaGetSymbolAddress((void**)&Kp, g_K);
    cudaGetSymbolAddress((void**)&Vp, g_V);
    cudaGetSymbolAddress((void**)&Ap, g_A);

    const dim3 gImg(DIM / 128, S_IMG / 128);
    const dim3 gTxt(DIM / 128, S_TXT / 128);

    // QKV projections into head layout (txt tokens at rows 0..511, img at 512..)
    sgemm_bias<0><<<gImg, 256>>>(hid, wq, bq, Qp, S_IMG, S_TXT);
    sgemm_bias<0><<<gImg, 256>>>(hid, wk, bk, Kp, S_IMG, S_TXT);
    sgemm_bias<0><<<gImg, 256>>>(hid, wv, bv, Vp, S_IMG, S_TXT);
    sgemm_bias<0><<<gTxt, 256>>>(enc, awq, abq, Qp, S_TXT, 0);
    sgemm_bias<0><<<gTxt, 256>>>(enc, awk, abk, Kp, S_TXT, 0);
    sgemm_bias<0><<<gTxt, 256>>>(enc, awv, abv, Vp, S_TXT, 0);

    // rmsnorm + rope on Q and K (V untouched)
    const int nr_blocks = (H * S_TOT) / 8;   // 8 warps per block
    norm_rope<<<nr_blocks, 256>>>(Qp, nq, anq, img_cos, img_sin, txt_cos, txt_sin);
    norm_rope<<<nr_blocks, 256>>>(Kp, nk, ank, img_cos, img_sin, txt_cos, txt_sin);

    // joint flash attention
    cudaFuncSetAttribute(flash_attn, cudaFuncAttributeMaxDynamicSharedMemorySize,
                         (int)FA_SMEM_BYTES);
    flash_attn<<<dim3(S_TOT / FA_BM, H), 256, FA_SMEM_BYTES>>>(Qp, Kp, Vp, Ap);

    // output projections: img rows of joint are 512.., txt rows 0..511
    sgemm_bias<1><<<gImg, 256>>>(Ap + (size_t)S_TXT * DIM, wo, bo, out, S_IMG, 0);
    sgemm_bias<1><<<gTxt, 256>>>(Ap, awo, abo, out + (size_t)S_IMG * DIM, S_TXT, 0);
}